// round 10
// baseline (speedup 1.0000x reference)
#include <cuda_runtime.h>
#include <cuda_bf16.h>
#include <math.h>
#include <stdint.h>

#define BATCH 2
#define LQ 13294
#define LEN_IN 13294
#define DM 256
#define NH 8
#define HD 32
#define MROWS (BATCH * LQ)   // 26588
#define MPAD  26624          // 208 * 128
#define QPR   64             // packed uint4 quads per row (16 chunks * 4 tg)
#define GRID_GEMM 456        // 3 CTAs/SM * 152 SMs (GB300)

// ---------------- scratch (device globals; no allocations allowed) ----------
__device__ float g_value[(size_t)BATCH * LEN_IN * DM];   // [B, LEN_IN, NH, HD]
__device__ float g_offs[(size_t)BATCH * LQ * DM];        // [B, LQ, NH, 16, 2]
__device__ float g_logits[(size_t)BATCH * LQ * NH * 16]; // [B, LQ, NH, 16]

__device__ uint4 g_Apack[(size_t)MPAD * QPR];            // inputf pack, reused for acc
__device__ uint4 g_Qpack[(size_t)MPAD * QPR];            // query pack
__device__ uint4 g_Wvp[256 * QPR];
__device__ uint4 g_Woffp[256 * QPR];
__device__ uint4 g_Wap[128 * QPR];
__device__ uint4 g_Woutp[256 * QPR];

// ---------------- helpers ---------------------------------------------------
__device__ __forceinline__ void mma_bf16(float* d,
    unsigned a0, unsigned a1, unsigned a2, unsigned a3,
    unsigned b0, unsigned b1)
{
    asm volatile(
        "mma.sync.aligned.m16n8k16.row.col.f32.bf16.bf16.f32 "
        "{%0,%1,%2,%3}, {%4,%5,%6,%7}, {%8,%9}, {%0,%1,%2,%3};"
        : "+f"(d[0]), "+f"(d[1]), "+f"(d[2]), "+f"(d[3])
        : "r"(a0), "r"(a1), "r"(a2), "r"(a3), "r"(b0), "r"(b1));
}

__device__ __forceinline__ void cpa16(uint32_t dst, const void* src) {
    asm volatile("cp.async.ca.shared.global [%0], [%1], 16;" :: "r"(dst), "l"(src));
}
#define CPA_COMMIT() asm volatile("cp.async.commit_group;")

__device__ __forceinline__ unsigned pack_hi2(float x0, float x1,
                                             float& l0, float& l1) {
    const __nv_bfloat16 h0 = __float2bfloat16_rn(x0);
    const __nv_bfloat16 h1 = __float2bfloat16_rn(x1);
    l0 = x0 - __bfloat162float(h0);
    l1 = x1 - __bfloat162float(h1);
    __nv_bfloat162 p; p.x = h0; p.y = h1;
    return *reinterpret_cast<unsigned*>(&p);
}
__device__ __forceinline__ unsigned pack_lo2(float l0, float l1) {
    __nv_bfloat162 p;
    p.x = __float2bfloat16_rn(l0);
    p.y = __float2bfloat16_rn(l1);
    return *reinterpret_cast<unsigned*>(&p);
}
__device__ __forceinline__ uint4 pack_quad(float x0, float x1, float x2, float x3) {
    float l0, l1, l2, l3;
    uint4 q;
    q.x = pack_hi2(x0, x1, l0, l1);
    q.y = pack_hi2(x2, x3, l2, l3);
    q.z = pack_lo2(l0, l1);
    q.w = pack_lo2(l2, l3);
    return q;
}

// ---------------- fused prepack (A0, A1, all weights in one launch) ----------
#define APART (2u * MPAD * 64u)
__global__ __launch_bounds__(256) void prepack_all(
    const float* __restrict__ A0, const float* __restrict__ A1,
    uint4* __restrict__ P0, uint4* __restrict__ P1,
    const float* __restrict__ Wv,  const float* __restrict__ Woff,
    const float* __restrict__ Wa,  const float* __restrict__ Wout,
    uint4* __restrict__ wvp, uint4* __restrict__ woffp,
    uint4* __restrict__ wap, uint4* __restrict__ woutp)
{
    const unsigned t = blockIdx.x * 256 + threadIdx.x;
    if (t < APART) {
        const unsigned HALF = (unsigned)MPAD * 64;
        const float* A = (t < HALF) ? A0 : A1;
        uint4* P = (t < HALF) ? P0 : P1;
        const unsigned lt = (t < HALF) ? t : t - HALF;
        const unsigned row = lt >> 6;
        const unsigned c = (lt >> 2) & 15, tg = lt & 3;
        float x0 = 0.f, x1 = 0.f, x2 = 0.f, x3 = 0.f;
        if (row < (unsigned)MROWS) {
            const float* a = A + (size_t)row * 256 + c * 16 + 2 * tg;
            x0 = a[0]; x1 = a[1]; x2 = a[8]; x3 = a[9];
        }
        P[lt] = pack_quad(x0, x1, x2, x3);
    } else {
        const unsigned u = t - APART;   // < 57344
        const float* B; uint4* Bp; unsigned N, lt;
        if (u < 16384)      { B = Wv;   Bp = wvp;   N = 256; lt = u; }
        else if (u < 32768) { B = Woff; Bp = woffp; N = 256; lt = u - 16384; }
        else if (u < 40960) { B = Wa;   Bp = wap;   N = 128; lt = u - 32768; }
        else                { B = Wout; Bp = woutp; N = 256; lt = u - 40960; }
        const unsigned col = lt >> 6;
        const unsigned c = (lt >> 2) & 15, tg = lt & 3;
        const unsigned k = c * 16 + 2 * tg;
        const float x0 = B[(k + 0) * N + col];
        const float x1 = B[(k + 1) * N + col];
        const float x2 = B[(k + 8) * N + col];
        const float x3 = B[(k + 9) * N + col];
        Bp[lt] = pack_quad(x0, x1, x2, x3);
    }
}

// ---------------- tensor-core GEMM tile (3xBF16 split, prepacked) -----------
// BM=128, BN=64, BK=32, 256 threads (8 warps: 2 M x 4 N), warp tile 64x16.
// Accumulator = 32 floats/thread -> regs fit 3 CTAs/SM.
#define RQ 12
#define ATQ (128 * RQ)                 // A tile quads (24 KB incl pad)
#define BTQ (64 * RQ)                  // B tile quads (12 KB incl pad)
#define STQ (ATQ + BTQ)                // stage quads
#define GSMEM_BYTES (2 * STQ * 16)     // 73728 B

struct GemmJob {
    const uint4* Ap;
    const uint4* Bp;
    const float* bias;
    float* C;
    int N;       // 256 or 128
    int ncols;   // N / 64
    int ntiles;  // ncols * 208
};

__device__ __forceinline__ void gemm_tile(
    const uint4* __restrict__ Ap, const uint4* __restrict__ Bp,
    const float* __restrict__ bias, float* __restrict__ C,
    int N, int bm, int bn, uint4* smem)
{
    const int tid = threadIdx.x;
    const int lane = tid & 31;
    const int wid = tid >> 5;
    const int warp_m = wid & 1;    // 0..1 -> 64 rows
    const int warp_n = wid >> 1;   // 0..3 -> 16 cols
    const int g  = lane >> 2;
    const int tg = lane & 3;

    const uint32_t smem_u32 = (uint32_t)__cvta_generic_to_shared(smem);
    const int NCH = 8;

    float acc[4][2][4];
    #pragma unroll
    for (int i = 0; i < 4; ++i)
        #pragma unroll
        for (int j = 0; j < 2; ++j)
            #pragma unroll
            for (int e = 0; e < 4; ++e) acc[i][j][e] = 0.f;

    auto load_tile = [&](int buf, int c) {
        const uint32_t abase = smem_u32 + (uint32_t)(buf * STQ) * 16;
        const uint32_t bbase = abase + (uint32_t)ATQ * 16;
        // A: 1024 quads, 4/thread
        #pragma unroll
        for (int p = 0; p < 4; ++p) {
            const int row = (tid >> 3) + p * 32;
            cpa16(abase + (uint32_t)(row * RQ + (tid & 7)) * 16,
                  Ap + (size_t)(bm + row) * QPR + c * 8 + (tid & 7));
        }
        // B: 512 quads, 2/thread
        #pragma unroll
        for (int p = 0; p < 2; ++p) {
            const int idx = tid + p * 256;
            const int col = idx >> 3, lf = idx & 7;
            cpa16(bbase + (uint32_t)(col * RQ + lf) * 16,
                  Bp + (size_t)(bn + col) * QPR + c * 8 + lf);
        }
        CPA_COMMIT();
    };

    load_tile(0, 0);

    for (int c = 0; c < NCH; ++c) {
        const int cur = c & 1;
        if (c + 1 < NCH) {
            load_tile(cur ^ 1, c + 1);
            asm volatile("cp.async.wait_group 1;");
        } else {
            asm volatile("cp.async.wait_group 0;");
        }
        __syncthreads();

        const uint4* As_ = smem + cur * STQ;
        const uint4* Bs_ = As_ + ATQ;

        #pragma unroll
        for (int cl = 0; cl < 2; ++cl) {
            const int qoff = cl * 4 + tg;
            uint4 bf[2];
            #pragma unroll
            for (int ni = 0; ni < 2; ++ni)
                bf[ni] = Bs_[(warp_n * 16 + ni * 8 + g) * RQ + qoff];

            #pragma unroll
            for (int mi = 0; mi < 4; ++mi) {
                const uint4 a0 = As_[(warp_m * 64 + mi * 16 + g) * RQ + qoff];
                const uint4 a1 = As_[(warp_m * 64 + mi * 16 + g + 8) * RQ + qoff];
                #pragma unroll
                for (int ni = 0; ni < 2; ++ni) {
                    mma_bf16(acc[mi][ni], a0.x, a1.x, a0.y, a1.y, bf[ni].x, bf[ni].y);
                    mma_bf16(acc[mi][ni], a0.x, a1.x, a0.y, a1.y, bf[ni].z, bf[ni].w);
                    mma_bf16(acc[mi][ni], a0.z, a1.z, a0.w, a1.w, bf[ni].x, bf[ni].y);
                }
            }
        }
        __syncthreads();   // protects smem reuse across chunks/tiles
    }

    #pragma unroll
    for (int mi = 0; mi < 4; ++mi) {
        const int row0 = bm + warp_m * 64 + mi * 16 + g;
        const int row1 = row0 + 8;
        #pragma unroll
        for (int ni = 0; ni < 2; ++ni) {
            const int col = bn + warp_n * 16 + ni * 8 + 2 * tg;
            const float bx = bias[col], by = bias[col + 1];
            if (row0 < MROWS) {
                float2 v = {acc[mi][ni][0] + bx, acc[mi][ni][1] + by};
                *reinterpret_cast<float2*>(C + (size_t)row0 * N + col) = v;
            }
            if (row1 < MROWS) {
                float2 v = {acc[mi][ni][2] + bx, acc[mi][ni][3] + by};
                *reinterpret_cast<float2*>(C + (size_t)row1 * N + col) = v;
            }
        }
    }
}

__global__ __launch_bounds__(256, 3) void fused_gemm_kernel(
    GemmJob j0, GemmJob j1, GemmJob j2, int njobs, int total)
{
    extern __shared__ uint4 smem[];
    for (int t = blockIdx.x; t < total; t += gridDim.x) {
        GemmJob jb = j0;
        int lt = t;
        if (njobs > 1 && lt >= jb.ntiles) {
            lt -= jb.ntiles; jb = j1;
            if (njobs > 2 && lt >= jb.ntiles) { lt -= jb.ntiles; jb = j2; }
        }
        int bm, bn;
        if (jb.ncols == 4) { bm = (lt >> 2) * 128; bn = (lt & 3) * 64; }
        else               { bm = (lt >> 1) * 128; bn = (lt & 1) * 64; }
        gemm_tile(jb.Ap, jb.Bp, jb.bias, jb.C, jb.N, bm, bn, smem);
    }
}

// ---------------- sampling + softmax + fused bf16 hi/lo packing -------------
// 2 queries per 512-thread block; one warp per (query, head); warps fully
// independent. Gather: sub = corner, cl = channel quad; per point one LDS.64 +
// one LDG.128 + 4 FFMA. Levels 0-1 __ldcg (L2-only), levels 2-3 __ldg.
__global__ __launch_bounds__(512) void sample_kernel(
    const float* __restrict__ refp, uint4* __restrict__ AccPack)
{
    __shared__ __align__(16) int2  comb[2][NH][16][4];
    __shared__ __align__(16) float swacc[2][NH][32];

    const int tid = threadIdx.x;
    const int q   = tid >> 8;                 // 0..1
    const int bq  = blockIdx.x * 2 + q;
    const int b   = (bq >= LQ) ? 1 : 0;
    const int h   = (tid >> 5) & 7;
    const int lane = tid & 31;

    // ---- softmax over the 16 logits ----
    float logit = -INFINITY;
    if (lane < 16) logit = g_logits[((unsigned)bq * NH + h) * 16 + lane];
    float m = logit;
    #pragma unroll
    for (int o = 16; o > 0; o >>= 1) m = fmaxf(m, __shfl_xor_sync(0xffffffffu, m, o));
    float e = (lane < 16) ? __expf(logit - m) : 0.f;
    float s = e;
    #pragma unroll
    for (int o = 16; o > 0; o >>= 1) s += __shfl_xor_sync(0xffffffffu, s, o);
    const float wt = e / s;

    if (lane < 16) {
        const int LH[4] = {100, 50, 25, 13};
        const int LS[4] = {0, 10000, 12500, 13125};
        const int l = lane >> 2;
        const int w = LH[l], hh = LH[l], s0 = LS[l];
        const float lw = (float)w, lh = (float)hh;

        const float2 off = *reinterpret_cast<const float2*>(
            g_offs + (((unsigned)bq * NH + h) * 16 + lane) * 2);
        const float2 rp = *reinterpret_cast<const float2*>(refp + (unsigned)bq * 8 + l * 2);

        const float x = (rp.x + off.x / lw) * lw - 0.5f;
        const float y = (rp.y + off.y / lh) * lh - 0.5f;
        const float fx = floorf(x), fy = floorf(y);
        const float tx = x - fx, ty = y - fy;
        const int jx = (int)fx, jy = (int)fy;

        const bool xv0 = (jx >= 0) && (jx < w);
        const bool xv1 = (jx + 1 >= 0) && (jx + 1 < w);
        const bool yv0 = (jy >= 0) && (jy < hh);
        const bool yv1 = (jy + 1 >= 0) && (jy + 1 < hh);

        const int cx0 = min(max(jx, 0), w - 1);
        const int cx1 = min(max(jx + 1, 0), w - 1);
        const int cy0 = min(max(jy, 0), hh - 1);
        const int cy1 = min(max(jy + 1, 0), hh - 1);

        const float wx1 = tx, wx0 = 1.f - tx;
        const float wy1 = ty, wy0 = 1.f - ty;

        const float w0 = (xv0 && yv0) ? wt * wx0 * wy0 : 0.f;
        const float w1 = (xv1 && yv0) ? wt * wx1 * wy0 : 0.f;
        const float w2 = (xv0 && yv1) ? wt * wx0 * wy1 : 0.f;
        const float w3 = (xv1 && yv1) ? wt * wx1 * wy1 : 0.f;

        comb[q][h][lane][0] = make_int2((s0 + cy0 * w + cx0) << 10, __float_as_int(w0));
        comb[q][h][lane][1] = make_int2((s0 + cy0 * w + cx1) << 10, __float_as_int(w1));
        comb[q][h][lane][2] = make_int2((s0 + cy1 * w + cx0) << 10, __float_as_int(w2));
        comb[q][h][lane][3] = make_int2((s0 + cy1 * w + cx1) << 10, __float_as_int(w3));
    }
    __syncwarp();

    // ---- vectorized gather ----
    const int sub = lane >> 3;
    const int cl  = lane & 7;
    const char* __restrict__ base = (const char*)(
        g_value + ((unsigned)b * LEN_IN) * DM + h * HD + cl * 4);

    float4 acc = {0.f, 0.f, 0.f, 0.f};
    #pragma unroll
    for (int p = 0; p < 16; ++p) {
        const int2 cw = comb[q][h][p][sub];
        float4 v;
        if (p < 8)   // levels 0-1: streaming, keep out of L1
            v = __ldcg(reinterpret_cast<const float4*>(base + cw.x));
        else          // levels 2-3: small working set, L1-resident
            v = __ldg(reinterpret_cast<const float4*>(base + cw.x));
        const float w = __int_as_float(cw.y);
        acc.x += w * v.x;
        acc.y += w * v.y;
        acc.z += w * v.z;
        acc.w += w * v.w;
    }

    #pragma unroll
    for (int o = 8; o <= 16; o <<= 1) {
        acc.x += __shfl_xor_sync(0xffffffffu, acc.x, o);
        acc.y += __shfl_xor_sync(0xffffffffu, acc.y, o);
        acc.z += __shfl_xor_sync(0xffffffffu, acc.z, o);
        acc.w += __shfl_xor_sync(0xffffffffu, acc.w, o);
    }
    if (sub == 0)
        *reinterpret_cast<float4*>(&swacc[q][h][cl * 4]) = acc;
    __syncwarp();

    // ---- pack this head's 32 channels into 8 bf16 hi/lo quads ----
    if (lane < 8) {
        const int cloc = lane >> 2, tg = lane & 3;
        const int bs = cloc * 16 + 2 * tg;
        AccPack[(size_t)bq * QPR + h * 8 + cloc * 4 + tg] =
            pack_quad(swacc[q][h][bs], swacc[q][h][bs + 1],
                      swacc[q][h][bs + 8], swacc[q][h][bs + 9]);
    }
}

// ---------------- launch ----------------------------------------------------
extern "C" void kernel_launch(void* const* d_in, const int* in_sizes, int n_in,
                              void* d_out, int out_size)
{
    const float* query  = (const float*)d_in[0];
    const float* refp   = (const float*)d_in[1];
    const float* inputf = (const float*)d_in[2];
    const float* Wv   = (const float*)d_in[4];
    const float* bv   = (const float*)d_in[5];
    const float* Woff = (const float*)d_in[6];
    const float* boff = (const float*)d_in[7];
    const float* Wa   = (const float*)d_in[8];
    const float* ba   = (const float*)d_in[9];
    const float* Wout = (const float*)d_in[10];
    const float* bout = (const float*)d_in[11];
    float* out = (float*)d_out;

    float *valuep, *offsp, *logitsp;
    uint4 *apackp, *qpackp, *wvp, *woffp, *wap, *woutp;
    cudaGetSymbolAddress((void**)&valuep,  g_value);
    cudaGetSymbolAddress((void**)&offsp,   g_offs);
    cudaGetSymbolAddress((void**)&logitsp, g_logits);
    cudaGetSymbolAddress((void**)&apackp,  g_Apack);
    cudaGetSymbolAddress((void**)&qpackp,  g_Qpack);
    cudaGetSymbolAddress((void**)&wvp,     g_Wvp);
    cudaGetSymbolAddress((void**)&woffp,   g_Woffp);
    cudaGetSymbolAddress((void**)&wap,     g_Wap);
    cudaGetSymbolAddress((void**)&woutp,   g_Woutp);

    static bool attr_set = false;
    if (!attr_set) {
        cudaFuncSetAttribute(fused_gemm_kernel,
                             cudaFuncAttributeMaxDynamicSharedMemorySize, GSMEM_BYTES);
        attr_set = true;
    }

    // fused prepack: A0, A1, all weights
    const unsigned npre = APART + 57344u;
    prepack_all<<<(npre + 255) / 256, 256>>>(
        inputf, query, apackp, qpackp,
        Wv, Woff, Wa, Wout, wvp, woffp, wap, woutp);

    // fused GEMMs 1-3: value / offs / logits  (832 + 832 + 416 = 2080 tiles)
    GemmJob jv  = {apackp, wvp,   bv,   valuep,  256, 4, 832};
    GemmJob jo  = {qpackp, woffp, boff, offsp,   256, 4, 832};
    GemmJob jl  = {qpackp, wap,   ba,   logitsp, 128, 2, 416};
    fused_gemm_kernel<<<GRID_GEMM, 256, GSMEM_BYTES>>>(jv, jo, jl, 3, 2080);

    // softmax + bilinear sampling -> packed acc (writes directly into Apack)
    sample_kernel<<<LQ, 512>>>(refp, apackp);

    // out = acc @ W_out + b_out
    GemmJob jout = {apackp, woutp, bout, out, 256, 4, 832};
    fused_gemm_kernel<<<GRID_GEMM, 256, GSMEM_BYTES>>>(jout, jout, jout, 1, 832);
}

// round 11
// speedup vs baseline: 1.1936x; 1.1936x over previous
#include <cuda_runtime.h>
#include <cuda_bf16.h>
#include <math.h>
#include <stdint.h>

#define BATCH 2
#define LQ 13294
#define LEN_IN 13294
#define DM 256
#define NH 8
#define HD 32
#define MROWS (BATCH * LQ)   // 26588
#define MPAD  26624          // 208 * 128
#define QPR   64             // packed uint4 quads per row (16 chunks * 4 tg)
#define GRID_GEMM 304        // 2 CTAs/SM * 152 SMs (GB300)

// ---------------- scratch (device globals; no allocations allowed) ----------
__device__ float g_value[(size_t)BATCH * LEN_IN * DM];   // [B, LEN_IN, NH, HD]
__device__ float g_offs[(size_t)BATCH * LQ * DM];        // [B, LQ, NH, 16, 2]
__device__ float g_logits[(size_t)BATCH * LQ * NH * 16]; // [B, LQ, NH, 16]

__device__ uint4 g_Apack[(size_t)MPAD * QPR];            // inputf pack, reused for acc
__device__ uint4 g_Qpack[(size_t)MPAD * QPR];            // query pack
__device__ uint4 g_Wvp[256 * QPR];
__device__ uint4 g_Woffp[256 * QPR];
__device__ uint4 g_Wap[128 * QPR];
__device__ uint4 g_Woutp[256 * QPR];

// ---------------- helpers ---------------------------------------------------
__device__ __forceinline__ void mma_bf16(float* d,
    unsigned a0, unsigned a1, unsigned a2, unsigned a3,
    unsigned b0, unsigned b1)
{
    asm volatile(
        "mma.sync.aligned.m16n8k16.row.col.f32.bf16.bf16.f32 "
        "{%0,%1,%2,%3}, {%4,%5,%6,%7}, {%8,%9}, {%0,%1,%2,%3};"
        : "+f"(d[0]), "+f"(d[1]), "+f"(d[2]), "+f"(d[3])
        : "r"(a0), "r"(a1), "r"(a2), "r"(a3), "r"(b0), "r"(b1));
}

__device__ __forceinline__ void cpa16(uint32_t dst, const void* src) {
    asm volatile("cp.async.ca.shared.global [%0], [%1], 16;" :: "r"(dst), "l"(src));
}
#define CPA_COMMIT() asm volatile("cp.async.commit_group;")

__device__ __forceinline__ unsigned pack_hi2(float x0, float x1,
                                             float& l0, float& l1) {
    const __nv_bfloat16 h0 = __float2bfloat16_rn(x0);
    const __nv_bfloat16 h1 = __float2bfloat16_rn(x1);
    l0 = x0 - __bfloat162float(h0);
    l1 = x1 - __bfloat162float(h1);
    __nv_bfloat162 p; p.x = h0; p.y = h1;
    return *reinterpret_cast<unsigned*>(&p);
}
__device__ __forceinline__ unsigned pack_lo2(float l0, float l1) {
    __nv_bfloat162 p;
    p.x = __float2bfloat16_rn(l0);
    p.y = __float2bfloat16_rn(l1);
    return *reinterpret_cast<unsigned*>(&p);
}
__device__ __forceinline__ uint4 pack_quad(float x0, float x1, float x2, float x3) {
    float l0, l1, l2, l3;
    uint4 q;
    q.x = pack_hi2(x0, x1, l0, l1);
    q.y = pack_hi2(x2, x3, l2, l3);
    q.z = pack_lo2(l0, l1);
    q.w = pack_lo2(l2, l3);
    return q;
}

// ---------------- fused prepack (A0, A1, all weights in one launch) ----------
#define APART (2u * MPAD * 64u)
__global__ __launch_bounds__(256) void prepack_all(
    const float* __restrict__ A0, const float* __restrict__ A1,
    uint4* __restrict__ P0, uint4* __restrict__ P1,
    const float* __restrict__ Wv,  const float* __restrict__ Woff,
    const float* __restrict__ Wa,  const float* __restrict__ Wout,
    uint4* __restrict__ wvp, uint4* __restrict__ woffp,
    uint4* __restrict__ wap, uint4* __restrict__ woutp)
{
    const unsigned t = blockIdx.x * 256 + threadIdx.x;
    if (t < APART) {
        const unsigned HALF = (unsigned)MPAD * 64;
        const float* A = (t < HALF) ? A0 : A1;
        uint4* P = (t < HALF) ? P0 : P1;
        const unsigned lt = (t < HALF) ? t : t - HALF;
        const unsigned row = lt >> 6;
        const unsigned c = (lt >> 2) & 15, tg = lt & 3;
        float x0 = 0.f, x1 = 0.f, x2 = 0.f, x3 = 0.f;
        if (row < (unsigned)MROWS) {
            const float* a = A + (size_t)row * 256 + c * 16 + 2 * tg;
            x0 = a[0]; x1 = a[1]; x2 = a[8]; x3 = a[9];
        }
        P[lt] = pack_quad(x0, x1, x2, x3);
    } else {
        const unsigned u = t - APART;   // < 57344
        const float* B; uint4* Bp; unsigned N, lt;
        if (u < 16384)      { B = Wv;   Bp = wvp;   N = 256; lt = u; }
        else if (u < 32768) { B = Woff; Bp = woffp; N = 256; lt = u - 16384; }
        else if (u < 40960) { B = Wa;   Bp = wap;   N = 128; lt = u - 32768; }
        else                { B = Wout; Bp = woutp; N = 256; lt = u - 40960; }
        const unsigned col = lt >> 6;
        const unsigned c = (lt >> 2) & 15, tg = lt & 3;
        const unsigned k = c * 16 + 2 * tg;
        const float x0 = B[(k + 0) * N + col];
        const float x1 = B[(k + 1) * N + col];
        const float x2 = B[(k + 8) * N + col];
        const float x3 = B[(k + 9) * N + col];
        Bp[lt] = pack_quad(x0, x1, x2, x3);
    }
}

// ---------------- tensor-core GEMM tile (3xBF16 split, prepacked) -----------
// BM=BN=128, BK=32, 256 threads (8 warps: 2 M x 4 N), warp tile 64x32.
#define RQ 12
#define TILE_QUADS (128 * RQ)                 // 1536 quads = 24 KB
#define GSMEM_BYTES (4 * TILE_QUADS * 16)     // 96 KB

struct GemmJob {
    const uint4* Ap;
    const uint4* Bp;
    const float* bias;
    float* C;
    int N;       // 256 or 128
    int ncols;   // N / 128
    int ntiles;  // ncols * 208
};

__device__ __forceinline__ void gemm_tile(
    const uint4* __restrict__ Ap, const uint4* __restrict__ Bp,
    const float* __restrict__ bias, float* __restrict__ C,
    int N, int bm, int bn, uint4* smem)
{
    const int tid = threadIdx.x;
    const int lane = tid & 31;
    const int wid = tid >> 5;
    const int warp_m = wid & 1;
    const int warp_n = wid >> 1;
    const int g  = lane >> 2;
    const int tg = lane & 3;

    const int lrow0 = tid >> 3;
    const int lf    = tid & 7;

    const uint32_t smem_u32 = (uint32_t)__cvta_generic_to_shared(smem);
    const int NCH = 8;

    float acc[4][4][4];
    #pragma unroll
    for (int i = 0; i < 4; ++i)
        #pragma unroll
        for (int j = 0; j < 4; ++j)
            #pragma unroll
            for (int e = 0; e < 4; ++e) acc[i][j][e] = 0.f;

    auto load_tile = [&](int buf, int c) {
        const uint32_t abase = smem_u32 + (uint32_t)(buf * 2 * TILE_QUADS) * 16;
        const uint32_t bbase = abase + (uint32_t)TILE_QUADS * 16;
        #pragma unroll
        for (int p = 0; p < 4; ++p) {
            const int row = lrow0 + p * 32;
            cpa16(abase + (uint32_t)(row * RQ + lf) * 16,
                  Ap + (size_t)(bm + row) * QPR + c * 8 + lf);
        }
        #pragma unroll
        for (int p = 0; p < 4; ++p) {
            const int col = lrow0 + p * 32;
            cpa16(bbase + (uint32_t)(col * RQ + lf) * 16,
                  Bp + (size_t)(bn + col) * QPR + c * 8 + lf);
        }
    };

    load_tile(0, 0);
    CPA_COMMIT();

    for (int c = 0; c < NCH; ++c) {
        const int cur = c & 1;
        if (c + 1 < NCH) {
            load_tile(cur ^ 1, c + 1);
            CPA_COMMIT();
            asm volatile("cp.async.wait_group 1;");
        } else {
            asm volatile("cp.async.wait_group 0;");
        }
        __syncthreads();

        const uint4* As_ = smem + cur * 2 * TILE_QUADS;
        const uint4* Bs_ = As_ + TILE_QUADS;

        #pragma unroll
        for (int cl = 0; cl < 2; ++cl) {
            const int qoff = cl * 4 + tg;
            uint4 bf[4];
            #pragma unroll
            for (int ni = 0; ni < 4; ++ni)
                bf[ni] = Bs_[(warp_n * 32 + ni * 8 + g) * RQ + qoff];

            #pragma unroll
            for (int mi = 0; mi < 4; ++mi) {
                const uint4 a0 = As_[(warp_m * 64 + mi * 16 + g) * RQ + qoff];
                const uint4 a1 = As_[(warp_m * 64 + mi * 16 + g + 8) * RQ + qoff];
                #pragma unroll
                for (int ni = 0; ni < 4; ++ni) {
                    mma_bf16(acc[mi][ni], a0.x, a1.x, a0.y, a1.y, bf[ni].x, bf[ni].y);
                    mma_bf16(acc[mi][ni], a0.x, a1.x, a0.y, a1.y, bf[ni].z, bf[ni].w);
                    mma_bf16(acc[mi][ni], a0.z, a1.z, a0.w, a1.w, bf[ni].x, bf[ni].y);
                }
            }
        }
        __syncthreads();   // protects smem reuse across chunks/tiles
    }

    // epilogue: bias hoisted to registers (one pair per ni), then guarded stores
    float bxr[4], byr[4];
    #pragma unroll
    for (int ni = 0; ni < 4; ++ni) {
        const int col = bn + warp_n * 32 + ni * 8 + 2 * tg;
        bxr[ni] = bias[col];
        byr[ni] = bias[col + 1];
    }
    #pragma unroll
    for (int mi = 0; mi < 4; ++mi) {
        const int row0 = bm + warp_m * 64 + mi * 16 + g;
        const int row1 = row0 + 8;
        #pragma unroll
        for (int ni = 0; ni < 4; ++ni) {
            const int col = bn + warp_n * 32 + ni * 8 + 2 * tg;
            if (row0 < MROWS) {
                float2 v = {acc[mi][ni][0] + bxr[ni], acc[mi][ni][1] + byr[ni]};
                *reinterpret_cast<float2*>(C + (size_t)row0 * N + col) = v;
            }
            if (row1 < MROWS) {
                float2 v = {acc[mi][ni][2] + bxr[ni], acc[mi][ni][3] + byr[ni]};
                *reinterpret_cast<float2*>(C + (size_t)row1 * N + col) = v;
            }
        }
    }
}

__global__ __launch_bounds__(256, 2) void fused_gemm_kernel(
    const GemmJob j0, const GemmJob j1, const GemmJob j2, int njobs, int total)
{
    extern __shared__ uint4 smem[];
    for (int t = blockIdx.x; t < total; t += gridDim.x) {
        GemmJob jb = j0;
        int lt = t;
        if (njobs > 1 && lt >= jb.ntiles) {
            lt -= jb.ntiles; jb = j1;
            if (njobs > 2 && lt >= jb.ntiles) { lt -= jb.ntiles; jb = j2; }
        }
        int bm, bn;
        if (jb.ncols == 2) { bm = (lt >> 1) * 128; bn = (lt & 1) * 128; }
        else               { bm = lt * 128;        bn = 0; }
        gemm_tile(jb.Ap, jb.Bp, jb.bias, jb.C, jb.N, bm, bn, smem);
    }
}

// ---------------- sampling + softmax + fused bf16 hi/lo packing -------------
// One block per (b,q); warps fully independent (one warp per head, no
// __syncthreads). Gather: sub = corner, cl = channel quad; per point one
// LDS.64 + one LDG.128 + 4 FFMA. Levels 0-1 __ldcg (L2-only, no L1
// pollution); levels 2-3 __ldg (small, L1-resident). Cross-corner reduce
// by shuffles; per-warp smem patch redistributes channels for the pack.
__global__ __launch_bounds__(256) void sample_kernel(
    const float* __restrict__ refp, uint4* __restrict__ AccPack)
{
    __shared__ __align__(16) int2  comb[NH][16][4];  // {byte offset, weight bits}
    __shared__ __align__(16) float swacc[NH][32];    // per-warp channel patch

    const int bq = blockIdx.x;
    const int b  = (bq >= LQ) ? 1 : 0;
    const int tid = threadIdx.x;
    const int h  = tid >> 5;
    const int lane = tid & 31;

    // ---- softmax over the 16 logits ----
    float logit = -INFINITY;
    if (lane < 16) logit = g_logits[((unsigned)bq * NH + h) * 16 + lane];
    float m = logit;
    #pragma unroll
    for (int o = 16; o > 0; o >>= 1) m = fmaxf(m, __shfl_xor_sync(0xffffffffu, m, o));
    float e = (lane < 16) ? __expf(logit - m) : 0.f;
    float s = e;
    #pragma unroll
    for (int o = 16; o > 0; o >>= 1) s += __shfl_xor_sync(0xffffffffu, s, o);
    const float wt = e / s;

    if (lane < 16) {
        const int LH[4] = {100, 50, 25, 13};
        const int LS[4] = {0, 10000, 12500, 13125};
        const int l = lane >> 2;
        const int w = LH[l], hh = LH[l], s0 = LS[l];
        const float lw = (float)w, lh = (float)hh;

        const float2 off = *reinterpret_cast<const float2*>(
            g_offs + (((unsigned)bq * NH + h) * 16 + lane) * 2);
        const float2 rp = *reinterpret_cast<const float2*>(refp + (unsigned)bq * 8 + l * 2);

        const float x = (rp.x + off.x / lw) * lw - 0.5f;
        const float y = (rp.y + off.y / lh) * lh - 0.5f;
        const float fx = floorf(x), fy = floorf(y);
        const float tx = x - fx, ty = y - fy;
        const int jx = (int)fx, jy = (int)fy;

        const bool xv0 = (jx >= 0) && (jx < w);
        const bool xv1 = (jx + 1 >= 0) && (jx + 1 < w);
        const bool yv0 = (jy >= 0) && (jy < hh);
        const bool yv1 = (jy + 1 >= 0) && (jy + 1 < hh);

        const int cx0 = min(max(jx, 0), w - 1);
        const int cx1 = min(max(jx + 1, 0), w - 1);
        const int cy0 = min(max(jy, 0), hh - 1);
        const int cy1 = min(max(jy + 1, 0), hh - 1);

        const float wx1 = tx, wx0 = 1.f - tx;
        const float wy1 = ty, wy0 = 1.f - ty;

        const float w0 = (xv0 && yv0) ? wt * wx0 * wy0 : 0.f;
        const float w1 = (xv1 && yv0) ? wt * wx1 * wy0 : 0.f;
        const float w2 = (xv0 && yv1) ? wt * wx0 * wy1 : 0.f;
        const float w3 = (xv1 && yv1) ? wt * wx1 * wy1 : 0.f;

        comb[h][lane][0] = make_int2((s0 + cy0 * w + cx0) << 10, __float_as_int(w0));
        comb[h][lane][1] = make_int2((s0 + cy0 * w + cx1) << 10, __float_as_int(w1));
        comb[h][lane][2] = make_int2((s0 + cy1 * w + cx0) << 10, __float_as_int(w2));
        comb[h][lane][3] = make_int2((s0 + cy1 * w + cx1) << 10, __float_as_int(w3));
    }
    __syncwarp();

    // ---- vectorized gather ----
    const int sub = lane >> 3;
    const int cl  = lane & 7;
    const char* __restrict__ base = (const char*)(
        g_value + ((unsigned)b * LEN_IN) * DM + h * HD + cl * 4);

    float4 acc = {0.f, 0.f, 0.f, 0.f};
    #pragma unroll
    for (int p = 0; p < 16; ++p) {
        const int2 cw = comb[h][p][sub];
        float4 v;
        if (p < 8)   // levels 0-1: streaming, keep out of L1
            v = __ldcg(reinterpret_cast<const float4*>(base + cw.x));
        else          // levels 2-3: small working set, L1-resident
            v = __ldg(reinterpret_cast<const float4*>(base + cw.x));
        const float w = __int_as_float(cw.y);
        acc.x += w * v.x;
        acc.y += w * v.y;
        acc.z += w * v.z;
        acc.w += w * v.w;
    }

    // reduce over the 4 corners (lanes cl, cl+8, cl+16, cl+24)
    #pragma unroll
    for (int o = 8; o <= 16; o <<= 1) {
        acc.x += __shfl_xor_sync(0xffffffffu, acc.x, o);
        acc.y += __shfl_xor_sync(0xffffffffu, acc.y, o);
        acc.z += __shfl_xor_sync(0xffffffffu, acc.z, o);
        acc.w += __shfl_xor_sync(0xffffffffu, acc.w, o);
    }
    if (sub == 0)
        *reinterpret_cast<float4*>(&swacc[h][cl * 4]) = acc;
    __syncwarp();

    // ---- pack this head's 32 channels into 8 bf16 hi/lo quads ----
    if (lane < 8) {
        const int cloc = lane >> 2, tg = lane & 3;
        const int bs = cloc * 16 + 2 * tg;
        AccPack[(size_t)bq * QPR + h * 8 + cloc * 4 + tg] =
            pack_quad(swacc[h][bs], swacc[h][bs + 1],
                      swacc[h][bs + 8], swacc[h][bs + 9]);
    }
}

// ---------------- launch ----------------------------------------------------
extern "C" void kernel_launch(void* const* d_in, const int* in_sizes, int n_in,
                              void* d_out, int out_size)
{
    const float* query  = (const float*)d_in[0];
    const float* refp   = (const float*)d_in[1];
    const float* inputf = (const float*)d_in[2];
    const float* Wv   = (const float*)d_in[4];
    const float* bv   = (const float*)d_in[5];
    const float* Woff = (const float*)d_in[6];
    const float* boff = (const float*)d_in[7];
    const float* Wa   = (const float*)d_in[8];
    const float* ba   = (const float*)d_in[9];
    const float* Wout = (const float*)d_in[10];
    const float* bout = (const float*)d_in[11];
    float* out = (float*)d_out;

    float *valuep, *offsp, *logitsp;
    uint4 *apackp, *qpackp, *wvp, *woffp, *wap, *woutp;
    cudaGetSymbolAddress((void**)&valuep,  g_value);
    cudaGetSymbolAddress((void**)&offsp,   g_offs);
    cudaGetSymbolAddress((void**)&logitsp, g_logits);
    cudaGetSymbolAddress((void**)&apackp,  g_Apack);
    cudaGetSymbolAddress((void**)&qpackp,  g_Qpack);
    cudaGetSymbolAddress((void**)&wvp,     g_Wvp);
    cudaGetSymbolAddress((void**)&woffp,   g_Woffp);
    cudaGetSymbolAddress((void**)&wap,     g_Wap);
    cudaGetSymbolAddress((void**)&woutp,   g_Woutp);

    static bool attr_set = false;
    if (!attr_set) {
        cudaFuncSetAttribute(fused_gemm_kernel,
                             cudaFuncAttributeMaxDynamicSharedMemorySize, GSMEM_BYTES);
        attr_set = true;
    }

    // fused prepack: A0, A1, all weights
    const unsigned npre = APART + 57344u;
    prepack_all<<<(npre + 255) / 256, 256>>>(
        inputf, query, apackp, qpackp,
        Wv, Woff, Wa, Wout, wvp, woffp, wap, woutp);

    // fused GEMMs 1-3: value / offs / logits  (416 + 416 + 208 = 1040 tiles)
    GemmJob jv  = {apackp, wvp,   bv,   valuep,  256, 2, 416};
    GemmJob jo  = {qpackp, woffp, boff, offsp,   256, 2, 416};
    GemmJob jl  = {qpackp, wap,   ba,   logitsp, 128, 1, 208};
    fused_gemm_kernel<<<GRID_GEMM, 256, GSMEM_BYTES>>>(jv, jo, jl, 3, 1040);

    // softmax + bilinear sampling -> packed acc (writes directly into Apack)
    sample_kernel<<<BATCH * LQ, 256>>>(refp, apackp);

    // out = acc @ W_out + b_out
    GemmJob jout = {apackp, woutp, bout, out, 256, 2, 416};
    fused_gemm_kernel<<<GRID_GEMM, 256, GSMEM_BYTES>>>(jout, jout, jout, 1, 416);
}